// round 7
// baseline (speedup 1.0000x reference)
#include <cuda_runtime.h>
#include <cstdint>
#include <math.h>

// ---------------- problem constants ----------------
#define Bdim 2
#define Nn   2048
#define Ff   64
#define Cc   64
#define Ll   4
#define Kk   (Nn*Ll)            // 8192
#define BM 128
#define BK 32                   // fp32 elements per K tile (128 bytes)
#define NTILES (Kk/BK)          // 256
#define SPLITK 13               // 32 M-tiles * 13 = 416 blocks = 1 wave @ 3/SM
#define PARTW 68                // 64 term3 + 4 deg

// ---------------- scratch (static device globals) ----------------
__device__ __align__(16) float g_W3VT[(size_t)Bdim*Cc*Kk];       // [b][c][k] (tf32 values)
__device__ __align__(16) float g_W2V [(size_t)Bdim*Nn*Ll*Cc];    // [m][l*64+c]
__device__ __align__(16) float g_T1  [(size_t)Bdim*Nn*Cc];
__device__ __align__(16) float g_WTh [576*Ff];                   // [t][f], tf32 hi
__device__ __align__(16) float g_WTl [576*Ff];                   // [t][f], tf32 lo
__device__ __align__(16) float g_part[(size_t)SPLITK*Bdim*Nn*PARTW];

// ---------------- helpers ----------------
__device__ __forceinline__ uint32_t smem_u32(const void* p) {
    uint32_t a;
    asm("{ .reg .u64 t; cvta.to.shared.u64 t, %1; cvt.u32.u64 %0, t; }" : "=r"(a) : "l"(p));
    return a;
}
__device__ __forceinline__ float to_tf32(float x) {
    uint32_t u;
    asm("cvt.rna.tf32.f32 %0, %1;" : "=r"(u) : "f"(x));
    return __uint_as_float(u);
}
__device__ __forceinline__ uint32_t sw128(uint32_t off) { return off ^ ((off >> 3) & 0x70); }

#define CP16(dst, src) \
    asm volatile("cp.async.cg.shared.global [%0], [%1], 16;" \
        :: "r"(dst), "l"(__cvta_generic_to_global(src)) : "memory")
#define CPCOMMIT() asm volatile("cp.async.commit_group;" ::: "memory")
#define CPWAIT(n)  asm volatile("cp.async.wait_group %0;" :: "n"(n) : "memory")

#define LDSM_X4(r, addr)                                                         \
    asm volatile("ldmatrix.sync.aligned.m8n8.x4.shared.b16 {%0,%1,%2,%3}, [%4];" \
        : "=r"((r)[0]), "=r"((r)[1]), "=r"((r)[2]), "=r"((r)[3]) : "r"(addr))

#define MMA_TF32(c, a, b0v, b1v)                                                 \
    asm volatile("mma.sync.aligned.m16n8k8.row.col.f32.tf32.tf32.f32 "           \
        "{%0,%1,%2,%3}, {%4,%5,%6,%7}, {%8,%9}, {%0,%1,%2,%3};"                  \
        : "+f"((c)[0]), "+f"((c)[1]), "+f"((c)[2]), "+f"((c)[3])                  \
        : "r"((a)[0]), "r"((a)[1]), "r"((a)[2]), "r"((a)[3]), "r"(b0v), "r"(b1v))

// ---------------- weight transpose/concat + tf32 split: g_WTh/g_WTl ----------------
// t<256: w3 (l=t>>6, c=t&63); 256<=t<512: w2; t>=512: w1 col (t-512)
__global__ void wtrans_kernel(const float* __restrict__ w1,
                              const float* __restrict__ w2,
                              const float* __restrict__ w3) {
    const int t = blockIdx.x, f = threadIdx.x;
    float v;
    if (t < 256)      v = w3[((t >> 6) * Ff + f) * Cc + (t & 63)];
    else if (t < 512) v = w2[(((t - 256) >> 6) * Ff + f) * Cc + ((t - 256) & 63)];
    else              v = w1[f * Cc + (t - 512)];
    const float hi = to_tf32(v);
    g_WTh[t * Ff + f] = hi;
    g_WTl[t * Ff + f] = to_tf32(v - hi);
}

// ---------------- precompute GEMM (tf32x3): [W3V | W2V | T1] = V @ Wcat ----------------
// grid (32 M-tiles, 9 N-chunks), 256 threads, warp tile 32x32.
__global__ __launch_bounds__(256)
void pregemm_kernel(const float* __restrict__ V) {
    __shared__ __align__(128) float sAhi[BM * BK];   // 16 KB
    __shared__ __align__(128) float sAlo[BM * BK];   // 16 KB
    __shared__ __align__(128) float sBhi[64 * BK];   //  8 KB
    __shared__ __align__(128) float sBlo[64 * BK];   //  8 KB  (total 48 KB)
    const uint32_t aH = smem_u32(sAhi), aL = smem_u32(sAlo);
    const uint32_t bH = smem_u32(sBhi), bL = smem_u32(sBlo);

    const int mtile = blockIdx.x, nc = blockIdx.y;
    const int m0 = mtile * BM;
    const int tid = threadIdx.x, wid = tid >> 5, lid = tid & 31;
    const int wm = wid & 3, wn = wid >> 2;

    const float* Ab  = V + (size_t)m0 * Ff;
    const float* Bh  = g_WTh + (size_t)nc * 64 * Ff;
    const float* Bl  = g_WTl + (size_t)nc * 64 * Ff;

    // ldmatrix quad addressing
    const int q = lid >> 3, rr = lid & 7;
    uint32_t aOff[2], bOff[2];
#pragma unroll
    for (int mt = 0; mt < 2; mt++)
        aOff[mt] = (uint32_t)((wm * 32 + mt * 16 + rr + (q & 1) * 8) * 128 + (q >> 1) * 16);
#pragma unroll
    for (int h = 0; h < 2; h++)
        bOff[h]  = (uint32_t)((wn * 32 + h * 16 + rr + (q >> 1) * 8) * 128 + (q & 1) * 16);

    float acc[2][4][4];
#pragma unroll
    for (int mt = 0; mt < 2; mt++)
#pragma unroll
        for (int nt = 0; nt < 4; nt++)
#pragma unroll
            for (int e = 0; e < 4; e++) acc[mt][nt][e] = 0.f;

    for (int kt = 0; kt < 2; kt++) {
        // stage A (hi/lo split)
#pragma unroll
        for (int it = 0; it < 4; it++) {
            const int idx = it * 256 + tid, row = idx >> 3, f4 = idx & 7;
            const float4 v = *(const float4*)(Ab + (size_t)row * Ff + kt * BK + f4 * 4);
            float4 h, l;
            h.x = to_tf32(v.x); l.x = to_tf32(v.x - h.x);
            h.y = to_tf32(v.y); l.y = to_tf32(v.y - h.y);
            h.z = to_tf32(v.z); l.z = to_tf32(v.z - h.z);
            h.w = to_tf32(v.w); l.w = to_tf32(v.w - h.w);
            const uint32_t off = sw128((uint32_t)(row * 128 + f4 * 16));
            *(float4*)((char*)sAhi + off) = h;
            *(float4*)((char*)sAlo + off) = l;
        }
        // stage B (already split in global)
#pragma unroll
        for (int it = 0; it < 2; it++) {
            const int idx = it * 256 + tid, row = idx >> 3, f4 = idx & 7;
            const uint32_t off = sw128((uint32_t)(row * 128 + f4 * 16));
            *(float4*)((char*)sBhi + off) = *(const float4*)(Bh + (size_t)row * Ff + kt * BK + f4 * 4);
            *(float4*)((char*)sBlo + off) = *(const float4*)(Bl + (size_t)row * Ff + kt * BK + f4 * 4);
        }
        __syncthreads();

#pragma unroll
        for (int ks = 0; ks < 4; ks++) {
            uint32_t afh[2][4], afl[2][4], bfh[2][4], bfl[2][4];
#pragma unroll
            for (int mt = 0; mt < 2; mt++) {
                uint32_t o = aOff[mt] + ks * 32, so = (o ^ ((o >> 3) & 0x70));
                LDSM_X4(afh[mt], aH + so);
                LDSM_X4(afl[mt], aL + so);
            }
#pragma unroll
            for (int h = 0; h < 2; h++) {
                uint32_t o = bOff[h] + ks * 32, so = (o ^ ((o >> 3) & 0x70));
                LDSM_X4(bfh[h], bH + so);
                LDSM_X4(bfl[h], bL + so);
            }
#pragma unroll
            for (int mt = 0; mt < 2; mt++)
#pragma unroll
                for (int nt = 0; nt < 4; nt++) {
                    const int hb = nt >> 1, eb = (nt & 1) * 2;
                    MMA_TF32(acc[mt][nt], afl[mt], bfh[hb][eb], bfh[hb][eb + 1]);
                    MMA_TF32(acc[mt][nt], afh[mt], bfl[hb][eb], bfl[hb][eb + 1]);
                    MMA_TF32(acc[mt][nt], afh[mt], bfh[hb][eb], bfh[hb][eb + 1]);
                }
        }
        __syncthreads();
    }

    // epilogue: route by N-chunk
    const int gid = lid >> 2, tig = lid & 3;
#pragma unroll
    for (int mt = 0; mt < 2; mt++)
#pragma unroll
        for (int nt = 0; nt < 4; nt++)
#pragma unroll
            for (int e = 0; e < 4; e++) {
                const int row = wm * 32 + mt * 16 + gid + (e >> 1) * 8;
                const int col = wn * 32 + nt * 8 + 2 * tig + (e & 1);
                const int m = m0 + row;
                const float v = acc[mt][nt][e];
                if (nc < 4) {
                    const int bb = m >> 11, j = m & 2047;
                    g_W3VT[((size_t)(bb * 64 + col)) * Kk + j * 4 + nc] = to_tf32(v);
                } else if (nc < 8) {
                    g_W2V[(size_t)m * 256 + (nc - 4) * 64 + col] = v;
                } else {
                    g_T1[(size_t)m * 64 + col] = v;
                }
            }
}

// ---------------- main GEMM: term3 + deg-from-fragments ----------------
// grid (16, Bdim, SPLITK), 256 threads (8 warps), warp tile 32x32.
__global__ __launch_bounds__(256, 3)
void gemm_kernel(const float* __restrict__ A) {
    __shared__ __align__(128) uint8_t smemRaw[49152];
    const uint32_t sm = smem_u32(smemRaw);
    const uint32_t sAu[2] = { sm, sm + 16384 };
    const uint32_t sBu[2] = { sm + 32768, sm + 40960 };
    float* degS = (float*)smemRaw;   // aliases sA0 after the main loop

    const int mtb = blockIdx.x, b = blockIdx.y, s = blockIdx.z;
    const int i0 = mtb * BM;
    const int t0 = (s * NTILES) / SPLITK, t1 = ((s + 1) * NTILES) / SPLITK;
    const int nkt = t1 - t0;
    const int tid = threadIdx.x, wid = tid >> 5, lid = tid & 31;
    const int wm = wid & 3, wn = wid >> 2;

    const float* Ab = A      + ((size_t)b * Nn + i0) * Kk;
    const float* Bb = g_W3VT + ((size_t)b * Cc) * Kk;

    auto issue = [&](int kt, int st) {
#pragma unroll
        for (int it = 0; it < 4; it++) {
            const int idx = it * 256 + tid, row = idx >> 3, f4 = idx & 7;
            CP16(sAu[st] + sw128((uint32_t)(row * 128 + f4 * 16)),
                 Ab + (size_t)row * Kk + kt * BK + f4 * 4);
        }
#pragma unroll
        for (int it = 0; it < 2; it++) {
            const int idx = it * 256 + tid, row = idx >> 3, f4 = idx & 7;
            CP16(sBu[st] + sw128((uint32_t)(row * 128 + f4 * 16)),
                 Bb + (size_t)row * Kk + kt * BK + f4 * 4);
        }
    };

    const int q = lid >> 3, rr = lid & 7;
    uint32_t aOff[2], bOff[2];
#pragma unroll
    for (int mt = 0; mt < 2; mt++)
        aOff[mt] = (uint32_t)((wm * 32 + mt * 16 + rr + (q & 1) * 8) * 128 + (q >> 1) * 16);
#pragma unroll
    for (int h = 0; h < 2; h++)
        bOff[h]  = (uint32_t)((wn * 32 + h * 16 + rr + (q >> 1) * 8) * 128 + (q & 1) * 16);

    float acc[2][4][4];
#pragma unroll
    for (int mt = 0; mt < 2; mt++)
#pragma unroll
        for (int nt = 0; nt < 4; nt++)
#pragma unroll
            for (int e = 0; e < 4; e++) acc[mt][nt][e] = 0.f;
    float dacc[4] = {0.f, 0.f, 0.f, 0.f};   // deg accum (wn==0 warps)

    issue(t0, 0); CPCOMMIT();
    if (nkt > 1) issue(t0 + 1, 1);
    CPCOMMIT();

    for (int qq = 0; qq < nkt; qq++) {
        const int st = qq & 1;
        CPWAIT(1);
        __syncthreads();
#pragma unroll
        for (int ks = 0; ks < 4; ks++) {
            uint32_t af[2][4], bf[2][4];
#pragma unroll
            for (int mt = 0; mt < 2; mt++) {
                uint32_t o = aOff[mt] + ks * 32;
                LDSM_X4(af[mt], sAu[st] + (o ^ ((o >> 3) & 0x70)));
            }
#pragma unroll
            for (int h = 0; h < 2; h++) {
                uint32_t o = bOff[h] + ks * 32;
                LDSM_X4(bf[h], sBu[st] + (o ^ ((o >> 3) & 0x70)));
            }
            if (wn == 0) {   // deg from A fragments: l = lane&3 exactly
#pragma unroll
                for (int mt = 0; mt < 2; mt++) {
                    dacc[mt * 2]     += __uint_as_float(af[mt][0]) + __uint_as_float(af[mt][2]);
                    dacc[mt * 2 + 1] += __uint_as_float(af[mt][1]) + __uint_as_float(af[mt][3]);
                }
            }
#pragma unroll
            for (int mt = 0; mt < 2; mt++)
#pragma unroll
                for (int nt = 0; nt < 4; nt++)
                    MMA_TF32(acc[mt][nt], af[mt], bf[nt >> 1][(nt & 1) * 2], bf[nt >> 1][(nt & 1) * 2 + 1]);
        }
        __syncthreads();
        if (qq + 2 < nkt) issue(t0 + qq + 2, st);
        CPCOMMIT();
    }

    // deg: unique (row, l) per thread among wn==0 warps -> plain stores
    const int gid = lid >> 2, tig = lid & 3;
    __syncthreads();
    if (wn == 0) {
#pragma unroll
        for (int i = 0; i < 4; i++) {
            const int row = wm * 32 + (i >> 1) * 16 + (i & 1) * 8 + gid;
            degS[row * 4 + tig] = dacc[i];
        }
    }
    __syncthreads();

    // write partials
    float* outp = g_part + (((size_t)s * Bdim + b) * Nn + i0) * PARTW;
#pragma unroll
    for (int mt = 0; mt < 2; mt++)
#pragma unroll
        for (int nt = 0; nt < 4; nt++) {
            const int r0 = wm * 32 + mt * 16 + gid;
            const int cc = wn * 32 + nt * 8 + 2 * tig;
            float2 v0; v0.x = acc[mt][nt][0]; v0.y = acc[mt][nt][1];
            float2 v1; v1.x = acc[mt][nt][2]; v1.y = acc[mt][nt][3];
            *(float2*)(outp + (size_t)r0 * PARTW + cc)       = v0;
            *(float2*)(outp + (size_t)(r0 + 8) * PARTW + cc) = v1;
        }
#pragma unroll
    for (int it = 0; it < 2; it++) {
        const int idx = it * 256 + tid;    // row*4 + l
        outp[(size_t)(idx >> 2) * PARTW + 64 + (idx & 3)] = degS[idx];
    }
}

// ---------------- epilogue: combine terms + sigmoid ----------------
// grid (Nn/8, Bdim), 256 threads: 8 rows/block, 32 threads/row, 2 channels each.
// All 13 slab reads batched into live register arrays BEFORE accumulation to
// force high MLP (the R6 version was compiler-capped at regs=32 -> MLP ~6).
__global__ __launch_bounds__(256)
void epilogue_kernel(float* __restrict__ out) {
    const int tid = threadIdx.x;
    const int lane = tid & 31, r = tid >> 5;
    const int i = blockIdx.x * 8 + r, b = blockIdx.y;
    const size_t row = (size_t)b * Nn + i;
    const int c = lane * 2;

    const float* base = g_part + ((size_t)b * Nn + i) * PARTW;
    float2 v[SPLITK];
    float4 dv[SPLITK];
#pragma unroll
    for (int s = 0; s < SPLITK; s++) {
        const float* p = base + (size_t)s * ((size_t)Bdim * Nn * PARTW);
        v[s]  = *(const float2*)(p + c);
        dv[s] = *(const float4*)(p + 64);
    }

    float t3a = 0.f, t3b = 0.f, d0 = 0.f, d1 = 0.f, d2 = 0.f, d3 = 0.f;
#pragma unroll
    for (int s = 0; s < SPLITK; s++) {
        t3a += v[s].x;  t3b += v[s].y;
        d0  += dv[s].x; d1  += dv[s].y; d2 += dv[s].z; d3 += dv[s].w;
    }

    const float* w2v = g_W2V + row * (Ll * Cc);
    const float2 w0 = *(const float2*)(w2v + 0 * Cc + c);
    const float2 w1 = *(const float2*)(w2v + 1 * Cc + c);
    const float2 w2 = *(const float2*)(w2v + 2 * Cc + c);
    const float2 w3 = *(const float2*)(w2v + 3 * Cc + c);
    const float2 t1 = *(const float2*)(g_T1 + row * Cc + c);

    const float xa = t1.x + d0 * w0.x + d1 * w1.x + d2 * w2.x + d3 * w3.x - t3a;
    const float xb = t1.y + d0 * w0.y + d1 * w1.y + d2 * w2.y + d3 * w3.y - t3b;
    float2 o;
    o.x = 1.f / (1.f + expf(-xa));
    o.y = 1.f / (1.f + expf(-xb));
    *(float2*)(out + row * Cc + c) = o;
}

// ---------------- launch ----------------
extern "C" void kernel_launch(void* const* d_in, const int* in_sizes, int n_in,
                              void* d_out, int out_size) {
    const float* V  = (const float*)d_in[0];
    const float* A  = (const float*)d_in[1];
    const float* w1 = (const float*)d_in[2];
    const float* w2 = (const float*)d_in[3];
    const float* w3 = (const float*)d_in[4];
    float* out = (float*)d_out;

    wtrans_kernel<<<576, 64>>>(w1, w2, w3);
    pregemm_kernel<<<dim3(32, 9), 256>>>(V);
    gemm_kernel<<<dim3(Nn / BM, Bdim, SPLITK), 256>>>(A);
    epilogue_kernel<<<dim3(Nn / 8, Bdim), 256>>>(out);
}

// round 8
// speedup vs baseline: 1.0724x; 1.0724x over previous
#include <cuda_runtime.h>
#include <cuda_fp16.h>
#include <cstdint>
#include <math.h>

// ---------------- problem constants ----------------
#define Bdim 2
#define Nn   2048
#define Ff   64
#define Cc   64
#define Ll   4
#define Kk   (Nn*Ll)            // 8192
#define BM 128
#define BKH 64                  // fp16 k-elements per tile (128 B rows)
#define NKTILES (Kk/BKH)        // 128
#define SPLITK 9                // 32 mtiles*9 = 288 blocks = 1 wave @ 2 CTA/SM
#define PARTW 68                // 64 term3 + 4 deg

// ---------------- scratch (static device globals) ----------------
__device__ __align__(16) __half g_W3VTh[(size_t)Bdim*Cc*Kk];     // [b][c][k] fp16
__device__ __align__(16) float g_W2V [(size_t)Bdim*Nn*Ll*Cc];
__device__ __align__(16) float g_T1  [(size_t)Bdim*Nn*Cc];
__device__ __align__(16) float g_WTh [576*Ff];                   // tf32 hi
__device__ __align__(16) float g_WTl [576*Ff];                   // tf32 lo
__device__ __align__(16) float g_part[(size_t)SPLITK*Bdim*Nn*PARTW];

// ---------------- helpers ----------------
__device__ __forceinline__ uint32_t smem_u32(const void* p) {
    uint32_t a;
    asm("{ .reg .u64 t; cvta.to.shared.u64 t, %1; cvt.u32.u64 %0, t; }" : "=r"(a) : "l"(p));
    return a;
}
__device__ __forceinline__ float to_tf32(float x) {
    uint32_t u;
    asm("cvt.rna.tf32.f32 %0, %1;" : "=r"(u) : "f"(x));
    return __uint_as_float(u);
}
__device__ __forceinline__ uint32_t sw128(uint32_t off) { return off ^ ((off >> 3) & 0x70); }
__device__ __forceinline__ uint32_t f22h2(float x, float y) {
    __half2 h = __floats2half2_rn(x, y);
    return *(uint32_t*)&h;
}

#define CP16(dst, src) \
    asm volatile("cp.async.cg.shared.global [%0], [%1], 16;" \
        :: "r"(dst), "l"(__cvta_generic_to_global(src)) : "memory")
#define CPCOMMIT() asm volatile("cp.async.commit_group;" ::: "memory")
#define CPWAIT(n)  asm volatile("cp.async.wait_group %0;" :: "n"(n) : "memory")

#define LDSM_X4(r, addr)                                                         \
    asm volatile("ldmatrix.sync.aligned.m8n8.x4.shared.b16 {%0,%1,%2,%3}, [%4];" \
        : "=r"((r)[0]), "=r"((r)[1]), "=r"((r)[2]), "=r"((r)[3]) : "r"(addr))

#define MMA_TF32(c, a, b0v, b1v)                                                 \
    asm volatile("mma.sync.aligned.m16n8k8.row.col.f32.tf32.tf32.f32 "           \
        "{%0,%1,%2,%3}, {%4,%5,%6,%7}, {%8,%9}, {%0,%1,%2,%3};"                  \
        : "+f"((c)[0]), "+f"((c)[1]), "+f"((c)[2]), "+f"((c)[3])                  \
        : "r"((a)[0]), "r"((a)[1]), "r"((a)[2]), "r"((a)[3]), "r"(b0v), "r"(b1v))

#define MMA_F16(c, a, b0v, b1v)                                                  \
    asm volatile("mma.sync.aligned.m16n8k16.row.col.f32.f16.f16.f32 "            \
        "{%0,%1,%2,%3}, {%4,%5,%6,%7}, {%8,%9}, {%0,%1,%2,%3};"                  \
        : "+f"((c)[0]), "+f"((c)[1]), "+f"((c)[2]), "+f"((c)[3])                  \
        : "r"((a)[0]), "r"((a)[1]), "r"((a)[2]), "r"((a)[3]), "r"(b0v), "r"(b1v))

// ---------------- weight transpose/concat + tf32 split ----------------
__global__ void wtrans_kernel(const float* __restrict__ w1,
                              const float* __restrict__ w2,
                              const float* __restrict__ w3) {
    const int t = blockIdx.x, f = threadIdx.x;
    float v;
    if (t < 256)      v = w3[((t >> 6) * Ff + f) * Cc + (t & 63)];
    else if (t < 512) v = w2[(((t - 256) >> 6) * Ff + f) * Cc + ((t - 256) & 63)];
    else              v = w1[f * Cc + (t - 512)];
    const float hi = to_tf32(v);
    g_WTh[t * Ff + f] = hi;
    g_WTl[t * Ff + f] = to_tf32(v - hi);
}

// ---------------- precompute GEMM (tf32x3): [W3V | W2V | T1] = V @ Wcat ----------------
__global__ __launch_bounds__(256)
void pregemm_kernel(const float* __restrict__ V) {
    __shared__ __align__(128) float sAhi[BM * 32];
    __shared__ __align__(128) float sAlo[BM * 32];
    __shared__ __align__(128) float sBhi[64 * 32];
    __shared__ __align__(128) float sBlo[64 * 32];
    const uint32_t aH = smem_u32(sAhi), aL = smem_u32(sAlo);
    const uint32_t bH = smem_u32(sBhi), bL = smem_u32(sBlo);

    const int mtile = blockIdx.x, nc = blockIdx.y;
    const int m0 = mtile * BM;
    const int tid = threadIdx.x, wid = tid >> 5, lid = tid & 31;
    const int wm = wid & 3, wn = wid >> 2;

    const float* Ab  = V + (size_t)m0 * Ff;
    const float* Bh  = g_WTh + (size_t)nc * 64 * Ff;
    const float* Bl  = g_WTl + (size_t)nc * 64 * Ff;

    const int q = lid >> 3, rr = lid & 7;
    uint32_t aOff[2], bOff[2];
#pragma unroll
    for (int mt = 0; mt < 2; mt++)
        aOff[mt] = (uint32_t)((wm * 32 + mt * 16 + rr + (q & 1) * 8) * 128 + (q >> 1) * 16);
#pragma unroll
    for (int h = 0; h < 2; h++)
        bOff[h]  = (uint32_t)((wn * 32 + h * 16 + rr + (q >> 1) * 8) * 128 + (q & 1) * 16);

    float acc[2][4][4];
#pragma unroll
    for (int mt = 0; mt < 2; mt++)
#pragma unroll
        for (int nt = 0; nt < 4; nt++)
#pragma unroll
            for (int e = 0; e < 4; e++) acc[mt][nt][e] = 0.f;

    for (int kt = 0; kt < 2; kt++) {
#pragma unroll
        for (int it = 0; it < 4; it++) {
            const int idx = it * 256 + tid, row = idx >> 3, f4 = idx & 7;
            const float4 v = *(const float4*)(Ab + (size_t)row * Ff + kt * 32 + f4 * 4);
            float4 h, l;
            h.x = to_tf32(v.x); l.x = to_tf32(v.x - h.x);
            h.y = to_tf32(v.y); l.y = to_tf32(v.y - h.y);
            h.z = to_tf32(v.z); l.z = to_tf32(v.z - h.z);
            h.w = to_tf32(v.w); l.w = to_tf32(v.w - h.w);
            const uint32_t off = sw128((uint32_t)(row * 128 + f4 * 16));
            *(float4*)((char*)sAhi + off) = h;
            *(float4*)((char*)sAlo + off) = l;
        }
#pragma unroll
        for (int it = 0; it < 2; it++) {
            const int idx = it * 256 + tid, row = idx >> 3, f4 = idx & 7;
            const uint32_t off = sw128((uint32_t)(row * 128 + f4 * 16));
            *(float4*)((char*)sBhi + off) = *(const float4*)(Bh + (size_t)row * Ff + kt * 32 + f4 * 4);
            *(float4*)((char*)sBlo + off) = *(const float4*)(Bl + (size_t)row * Ff + kt * 32 + f4 * 4);
        }
        __syncthreads();

#pragma unroll
        for (int ks = 0; ks < 4; ks++) {
            uint32_t afh[2][4], afl[2][4], bfh[2][4], bfl[2][4];
#pragma unroll
            for (int mt = 0; mt < 2; mt++) {
                uint32_t o = aOff[mt] + ks * 32, so = (o ^ ((o >> 3) & 0x70));
                LDSM_X4(afh[mt], aH + so);
                LDSM_X4(afl[mt], aL + so);
            }
#pragma unroll
            for (int h = 0; h < 2; h++) {
                uint32_t o = bOff[h] + ks * 32, so = (o ^ ((o >> 3) & 0x70));
                LDSM_X4(bfh[h], bH + so);
                LDSM_X4(bfl[h], bL + so);
            }
#pragma unroll
            for (int mt = 0; mt < 2; mt++)
#pragma unroll
                for (int nt = 0; nt < 4; nt++) {
                    const int hb = nt >> 1, eb = (nt & 1) * 2;
                    MMA_TF32(acc[mt][nt], afl[mt], bfh[hb][eb], bfh[hb][eb + 1]);
                    MMA_TF32(acc[mt][nt], afh[mt], bfl[hb][eb], bfl[hb][eb + 1]);
                    MMA_TF32(acc[mt][nt], afh[mt], bfh[hb][eb], bfh[hb][eb + 1]);
                }
        }
        __syncthreads();
    }

    const int gid = lid >> 2, tig = lid & 3;
#pragma unroll
    for (int mt = 0; mt < 2; mt++)
#pragma unroll
        for (int nt = 0; nt < 4; nt++)
#pragma unroll
            for (int e = 0; e < 4; e++) {
                const int row = wm * 32 + mt * 16 + gid + (e >> 1) * 8;
                const int col = wn * 32 + nt * 8 + 2 * tig + (e & 1);
                const int m = m0 + row;
                const float v = acc[mt][nt][e];
                if (nc < 4) {
                    const int bb = m >> 11, j = m & 2047;
                    g_W3VTh[((size_t)(bb * 64 + col)) * Kk + j * 4 + nc] = __float2half_rn(v);
                } else if (nc < 8) {
                    g_W2V[(size_t)m * 256 + (nc - 4) * 64 + col] = v;
                } else {
                    g_T1[(size_t)m * 64 + col] = v;
                }
            }
}

// ---------------- main GEMM: fp16 m16n8k16, term3 + deg-from-fragments ----------------
// grid (16, Bdim, SPLITK), 256 threads (8 warps), warp tile 32 rows x 32 n.
// A: LDG fp32 -> cvt fp16 -> STS (regs). B: cp.async fp16 direct.
__global__ __launch_bounds__(256, 2)
void gemm_kernel(const float* __restrict__ A) {
    __shared__ __align__(128) uint8_t smemRaw[49152];  // A:2x16KB, B:2x8KB
    const uint32_t sm = smem_u32(smemRaw);
    const uint32_t sAu[2] = { sm, sm + 16384 };
    const uint32_t sBu[2] = { sm + 32768, sm + 40960 };
    float* degS = (float*)smemRaw;   // aliases sA0 after the main loop

    const int mtb = blockIdx.x, b = blockIdx.y, s = blockIdx.z;
    const int i0 = mtb * BM;
    const int t0 = (s * NKTILES) / SPLITK, t1 = ((s + 1) * NKTILES) / SPLITK;
    const int nkt = t1 - t0;
    const int tid = threadIdx.x, wid = tid >> 5, lid = tid & 31;
    const int wm = wid & 3, wn = wid >> 2;

    const float*  Ab = A + ((size_t)b * Nn + i0) * Kk;
    const __half* Bb = g_W3VTh + ((size_t)b * Cc) * Kk;

    float4 ra[8];
    auto loadA = [&](int kt) {
#pragma unroll
        for (int it = 0; it < 8; it++) {
            const int idx = it * 256 + tid, row = idx >> 4, f4 = idx & 15;
            ra[it] = *(const float4*)(Ab + (size_t)row * Kk + kt * BKH + f4 * 4);
        }
    };
    auto stageA = [&](int st) {
#pragma unroll
        for (int it = 0; it < 8; it++) {
            const int idx = it * 256 + tid, row = idx >> 4, f4 = idx & 15;
            const uint32_t off = sw128((uint32_t)(row * 128 + f4 * 8));
            uint2 hv;
            hv.x = f22h2(ra[it].x, ra[it].y);
            hv.y = f22h2(ra[it].z, ra[it].w);
            *(uint2*)(smemRaw + st * 16384 + off) = hv;
        }
    };
    auto issueB = [&](int kt, int st) {
#pragma unroll
        for (int it = 0; it < 2; it++) {
            const int idx = it * 256 + tid, row = idx >> 3, seg = idx & 7;
            CP16(sBu[st] + sw128((uint32_t)(row * 128 + seg * 16)),
                 Bb + (size_t)row * Kk + kt * BKH + seg * 8);
        }
    };

    // ldmatrix x4 addressing: 16 rows x 16 fp16; lane l -> tile q = l>>3
    // q&1 -> row half, l>>4 -> k half (16 B = 8 fp16)
    const uint32_t lrow = (uint32_t)((lid & 7) + ((lid >> 3) & 1) * 8);
    const uint32_t lkof = (uint32_t)((lid >> 4) * 16);
    uint32_t aOff[2], bOff[2];
#pragma unroll
    for (int mt = 0; mt < 2; mt++)
        aOff[mt] = (wm * 32 + mt * 16 + lrow) * 128 + lkof;
#pragma unroll
    for (int h = 0; h < 2; h++)
        bOff[h]  = (wn * 32 + h * 16 + lrow) * 128 + lkof;

    float acc[2][4][4];
#pragma unroll
    for (int mt = 0; mt < 2; mt++)
#pragma unroll
        for (int nt = 0; nt < 4; nt++)
#pragma unroll
            for (int e = 0; e < 4; e++) acc[mt][nt][e] = 0.f;
    // deg accumulators: [mt][row-half], components = e pair (e = 2*(lid&1) + {0,1})
    float2 dacc[2][2];
#pragma unroll
    for (int mt = 0; mt < 2; mt++)
#pragma unroll
        for (int rh = 0; rh < 2; rh++) { dacc[mt][rh].x = 0.f; dacc[mt][rh].y = 0.f; }

    loadA(t0);
    issueB(t0, 0); CPCOMMIT();
    if (nkt > 1) issueB(t0 + 1, 1);
    CPCOMMIT();

    for (int qq = 0; qq < nkt; qq++) {
        const int st = qq & 1;
        stageA(st);
        if (qq + 1 < nkt) loadA(t0 + qq + 1);
        CPWAIT(1);
        __syncthreads();

#pragma unroll
        for (int ks = 0; ks < 4; ks++) {
            uint32_t af[2][4], bf[2][4];
#pragma unroll
            for (int mt = 0; mt < 2; mt++) {
                uint32_t o = aOff[mt] + ks * 32;
                LDSM_X4(af[mt], sAu[st] + (o ^ ((o >> 3) & 0x70)));
            }
#pragma unroll
            for (int h = 0; h < 2; h++) {
                uint32_t o = bOff[h] + ks * 32;
                LDSM_X4(bf[h], sBu[st] + (o ^ ((o >> 3) & 0x70)));
            }
            if (wn == 0) {   // deg: each fp16 pair has k&3 = 2*(lid&1) + {0,1}
#pragma unroll
                for (int mt = 0; mt < 2; mt++)
#pragma unroll
                    for (int r = 0; r < 4; r++) {
                        const __half2 h = *(__half2*)&af[mt][r];
                        const float2 f = __half22float2(h);
                        dacc[mt][r & 1].x += f.x;
                        dacc[mt][r & 1].y += f.y;
                    }
            }
#pragma unroll
            for (int mt = 0; mt < 2; mt++)
#pragma unroll
                for (int nt = 0; nt < 4; nt++)
                    MMA_F16(acc[mt][nt], af[mt],
                            bf[nt >> 1][nt & 1], bf[nt >> 1][(nt & 1) + 2]);
        }
        __syncthreads();
        if (qq + 2 < nkt) issueB(t0 + qq + 2, st);
        CPCOMMIT();
    }

    // deg: combine lanes l and l^2 (same row, same e-pair, different k), write once
    if (wn == 0) {
#pragma unroll
        for (int mt = 0; mt < 2; mt++)
#pragma unroll
            for (int rh = 0; rh < 2; rh++) {
                float sx = dacc[mt][rh].x + __shfl_xor_sync(0xFFFFFFFFu, dacc[mt][rh].x, 2);
                float sy = dacc[mt][rh].y + __shfl_xor_sync(0xFFFFFFFFu, dacc[mt][rh].y, 2);
                if ((lid & 2) == 0) {
                    const int row = wm * 32 + mt * 16 + rh * 8 + (lid >> 2);
                    const int e0 = 2 * (lid & 1);
                    degS[row * 4 + e0]     = sx;
                    degS[row * 4 + e0 + 1] = sy;
                }
            }
    }
    __syncthreads();

    // write partials
    const int gid = lid >> 2, tig = lid & 3;
    float* outp = g_part + (((size_t)s * Bdim + b) * Nn + i0) * PARTW;
#pragma unroll
    for (int mt = 0; mt < 2; mt++)
#pragma unroll
        for (int nt = 0; nt < 4; nt++) {
            const int r0 = wm * 32 + mt * 16 + gid;
            const int cc = wn * 32 + nt * 8 + 2 * tig;
            float2 v0; v0.x = acc[mt][nt][0]; v0.y = acc[mt][nt][1];
            float2 v1; v1.x = acc[mt][nt][2]; v1.y = acc[mt][nt][3];
            *(float2*)(outp + (size_t)r0 * PARTW + cc)       = v0;
            *(float2*)(outp + (size_t)(r0 + 8) * PARTW + cc) = v1;
        }
#pragma unroll
    for (int it = 0; it < 2; it++) {
        const int idx = it * 256 + tid;    // row*4 + l
        outp[(size_t)(idx >> 2) * PARTW + 64 + (idx & 3)] = degS[idx];
    }
}

// ---------------- epilogue: asm-forced MLP + lane-parallel deg reduce ----------------
// grid (Nn/8, Bdim), 256 threads: 1 warp per row, 2 channels per lane.
__global__ __launch_bounds__(256)
void epilogue_kernel(float* __restrict__ out) {
    const int tid = threadIdx.x;
    const int lane = tid & 31, r = tid >> 5;
    const int i = blockIdx.x * 8 + r, b = blockIdx.y;
    const size_t row = (size_t)b * Nn + i;
    const int c = lane * 2;
    const size_t stride = (size_t)Bdim * Nn * PARTW;
    const float* base = g_part + ((size_t)b * Nn + i) * PARTW;

    // forced-order loads: ptxas cannot sink or interleave volatile asm
    float vx[SPLITK], vy[SPLITK];
#pragma unroll
    for (int s = 0; s < SPLITK; s++) {
        const float* p = base + s * stride + c;
        asm volatile("ld.global.nc.v2.f32 {%0, %1}, [%2];"
                     : "=f"(vx[s]), "=f"(vy[s]) : "l"(p));
    }
    // deg: lanes 0..SPLITK-1 each load one slab's float4, butterfly-sum to all lanes
    float4 dv = make_float4(0.f, 0.f, 0.f, 0.f);
    if (lane < SPLITK)
        dv = *(const float4*)(base + lane * stride + 64);
#pragma unroll
    for (int off = 16; off > 0; off >>= 1) {
        dv.x += __shfl_xor_sync(0xFFFFFFFFu, dv.x, off);
        dv.y += __shfl_xor_sync(0xFFFFFFFFu, dv.y, off);
        dv.z += __shfl_xor_sync(0xFFFFFFFFu, dv.z, off);
        dv.w += __shfl_xor_sync(0xFFFFFFFFu, dv.w, off);
    }

    float t3a = 0.f, t3b = 0.f;
#pragma unroll
    for (int s = 0; s < SPLITK; s++) { t3a += vx[s]; t3b += vy[s]; }

    const float* w2v = g_W2V + row * (Ll * Cc);
    const float2 w0 = *(const float2*)(w2v + 0 * Cc + c);
    const float2 w1 = *(const float2*)(w2v + 1 * Cc + c);
    const float2 w2 = *(const float2*)(w2v + 2 * Cc + c);
    const float2 w3 = *(const float2*)(w2v + 3 * Cc + c);
    const float2 t1 = *(const float2*)(g_T1 + row * Cc + c);

    const float xa = t1.x + dv.x * w0.x + dv.y * w1.x + dv.z * w2.x + dv.w * w3.x - t3a;
    const float xb = t1.y + dv.x * w0.y + dv.y * w1.y + dv.z * w2.y + dv.w * w3.y - t3b;
    float2 o;
    o.x = 1.f / (1.f + expf(-xa));
    o.y = 1.f / (1.f + expf(-xb));
    *(float2*)(out + row * Cc + c) = o;
}

// ---------------- launch ----------------
extern "C" void kernel_launch(void* const* d_in, const int* in_sizes, int n_in,
                              void* d_out, int out_size) {
    const float* V  = (const float*)d_in[0];
    const float* A  = (const float*)d_in[1];
    const float* w1 = (const float*)d_in[2];
    const float* w2 = (const float*)d_in[3];
    const float* w3 = (const float*)d_in[4];
    float* out = (float*)d_out;

    wtrans_kernel<<<576, 64>>>(w1, w2, w3);
    pregemm_kernel<<<dim3(32, 9), 256>>>(V);
    gemm_kernel<<<dim3(Nn / BM, Bdim, SPLITK), 256>>>(A);
    epilogue_kernel<<<dim3(Nn / 8, Bdim), 256>>>(out);
}

// round 9
// speedup vs baseline: 1.0731x; 1.0006x over previous
#include <cuda_runtime.h>
#include <cuda_fp16.h>
#include <cstdint>
#include <math.h>

// ---------------- problem constants ----------------
#define Bdim 2
#define Nn   2048
#define Ff   64
#define Cc   64
#define Ll   4
#define Kk   (Nn*Ll)            // 8192
#define BM 64                   // rows per block (4 CTA/SM)
#define BKH 64                  // fp16 k-elements per tile (128 B rows)
#define NKTILES (Kk/BKH)        // 128
#define SPLITK 9                // 32 mtiles*2*9 = 576 blocks = 1 wave @ 4 CTA/SM
#define PARTW 68                // 64 term3 + 4 deg

// ---------------- scratch (static device globals) ----------------
__device__ __align__(16) __half g_W3VTh[(size_t)Bdim*Cc*Kk];     // [b][c][k] fp16
__device__ __align__(16) float g_W2V [(size_t)Bdim*Nn*Ll*Cc];
__device__ __align__(16) float g_T1  [(size_t)Bdim*Nn*Cc];
__device__ __align__(16) float g_WTh [576*Ff];                   // tf32 hi
__device__ __align__(16) float g_WTl [576*Ff];                   // tf32 lo
__device__ __align__(16) float g_part[(size_t)SPLITK*Bdim*Nn*PARTW];

// ---------------- helpers ----------------
__device__ __forceinline__ uint32_t smem_u32(const void* p) {
    uint32_t a;
    asm("{ .reg .u64 t; cvta.to.shared.u64 t, %1; cvt.u32.u64 %0, t; }" : "=r"(a) : "l"(p));
    return a;
}
__device__ __forceinline__ float to_tf32(float x) {
    uint32_t u;
    asm("cvt.rna.tf32.f32 %0, %1;" : "=r"(u) : "f"(x));
    return __uint_as_float(u);
}
__device__ __forceinline__ uint32_t sw128(uint32_t off) { return off ^ ((off >> 3) & 0x70); }
__device__ __forceinline__ uint32_t f22h2(float x, float y) {
    __half2 h = __floats2half2_rn(x, y);
    return *(uint32_t*)&h;
}

#define CP16(dst, src) \
    asm volatile("cp.async.cg.shared.global [%0], [%1], 16;" \
        :: "r"(dst), "l"(__cvta_generic_to_global(src)) : "memory")
#define CPCOMMIT() asm volatile("cp.async.commit_group;" ::: "memory")
#define CPWAIT(n)  asm volatile("cp.async.wait_group %0;" :: "n"(n) : "memory")

#define LDSM_X4(r, addr)                                                         \
    asm volatile("ldmatrix.sync.aligned.m8n8.x4.shared.b16 {%0,%1,%2,%3}, [%4];" \
        : "=r"((r)[0]), "=r"((r)[1]), "=r"((r)[2]), "=r"((r)[3]) : "r"(addr))

#define MMA_TF32(c, a, b0v, b1v)                                                 \
    asm volatile("mma.sync.aligned.m16n8k8.row.col.f32.tf32.tf32.f32 "           \
        "{%0,%1,%2,%3}, {%4,%5,%6,%7}, {%8,%9}, {%0,%1,%2,%3};"                  \
        : "+f"((c)[0]), "+f"((c)[1]), "+f"((c)[2]), "+f"((c)[3])                  \
        : "r"((a)[0]), "r"((a)[1]), "r"((a)[2]), "r"((a)[3]), "r"(b0v), "r"(b1v))

#define MMA_F16(c, a, b0v, b1v)                                                  \
    asm volatile("mma.sync.aligned.m16n8k16.row.col.f32.f16.f16.f32 "            \
        "{%0,%1,%2,%3}, {%4,%5,%6,%7}, {%8,%9}, {%0,%1,%2,%3};"                  \
        : "+f"((c)[0]), "+f"((c)[1]), "+f"((c)[2]), "+f"((c)[3])                  \
        : "r"((a)[0]), "r"((a)[1]), "r"((a)[2]), "r"((a)[3]), "r"(b0v), "r"(b1v))

// ---------------- weight transpose/concat + tf32 split ----------------
__global__ void wtrans_kernel(const float* __restrict__ w1,
                              const float* __restrict__ w2,
                              const float* __restrict__ w3) {
    const int t = blockIdx.x, f = threadIdx.x;
    float v;
    if (t < 256)      v = w3[((t >> 6) * Ff + f) * Cc + (t & 63)];
    else if (t < 512) v = w2[(((t - 256) >> 6) * Ff + f) * Cc + ((t - 256) & 63)];
    else              v = w1[f * Cc + (t - 512)];
    const float hi = to_tf32(v);
    g_WTh[t * Ff + f] = hi;
    g_WTl[t * Ff + f] = to_tf32(v - hi);
}

// ---------------- precompute GEMM (tf32x3): [W3V | W2V | T1] = V @ Wcat ----------------
// grid (32 M-tiles of 128 rows, 9 N-chunks), 256 threads.
__global__ __launch_bounds__(256)
void pregemm_kernel(const float* __restrict__ V) {
    __shared__ __align__(128) float sAhi[128 * 32];
    __shared__ __align__(128) float sAlo[128 * 32];
    __shared__ __align__(128) float sBhi[64 * 32];
    __shared__ __align__(128) float sBlo[64 * 32];
    const uint32_t aH = smem_u32(sAhi), aL = smem_u32(sAlo);
    const uint32_t bH = smem_u32(sBhi), bL = smem_u32(sBlo);

    const int mtile = blockIdx.x, nc = blockIdx.y;
    const int m0 = mtile * 128;
    const int tid = threadIdx.x, wid = tid >> 5, lid = tid & 31;
    const int wm = wid & 3, wn = wid >> 2;

    const float* Ab  = V + (size_t)m0 * Ff;
    const float* Bh  = g_WTh + (size_t)nc * 64 * Ff;
    const float* Bl  = g_WTl + (size_t)nc * 64 * Ff;

    const int q = lid >> 3, rr = lid & 7;
    uint32_t aOff[2], bOff[2];
#pragma unroll
    for (int mt = 0; mt < 2; mt++)
        aOff[mt] = (uint32_t)((wm * 32 + mt * 16 + rr + (q & 1) * 8) * 128 + (q >> 1) * 16);
#pragma unroll
    for (int h = 0; h < 2; h++)
        bOff[h]  = (uint32_t)((wn * 32 + h * 16 + rr + (q >> 1) * 8) * 128 + (q & 1) * 16);

    float acc[2][4][4];
#pragma unroll
    for (int mt = 0; mt < 2; mt++)
#pragma unroll
        for (int nt = 0; nt < 4; nt++)
#pragma unroll
            for (int e = 0; e < 4; e++) acc[mt][nt][e] = 0.f;

    for (int kt = 0; kt < 2; kt++) {
#pragma unroll
        for (int it = 0; it < 4; it++) {
            const int idx = it * 256 + tid, row = idx >> 3, f4 = idx & 7;
            const float4 v = *(const float4*)(Ab + (size_t)row * Ff + kt * 32 + f4 * 4);
            float4 h, l;
            h.x = to_tf32(v.x); l.x = to_tf32(v.x - h.x);
            h.y = to_tf32(v.y); l.y = to_tf32(v.y - h.y);
            h.z = to_tf32(v.z); l.z = to_tf32(v.z - h.z);
            h.w = to_tf32(v.w); l.w = to_tf32(v.w - h.w);
            const uint32_t off = sw128((uint32_t)(row * 128 + f4 * 16));
            *(float4*)((char*)sAhi + off) = h;
            *(float4*)((char*)sAlo + off) = l;
        }
#pragma unroll
        for (int it = 0; it < 2; it++) {
            const int idx = it * 256 + tid, row = idx >> 3, f4 = idx & 7;
            const uint32_t off = sw128((uint32_t)(row * 128 + f4 * 16));
            *(float4*)((char*)sBhi + off) = *(const float4*)(Bh + (size_t)row * Ff + kt * 32 + f4 * 4);
            *(float4*)((char*)sBlo + off) = *(const float4*)(Bl + (size_t)row * Ff + kt * 32 + f4 * 4);
        }
        __syncthreads();

#pragma unroll
        for (int ks = 0; ks < 4; ks++) {
            uint32_t afh[2][4], afl[2][4], bfh[2][4], bfl[2][4];
#pragma unroll
            for (int mt = 0; mt < 2; mt++) {
                uint32_t o = aOff[mt] + ks * 32, so = (o ^ ((o >> 3) & 0x70));
                LDSM_X4(afh[mt], aH + so);
                LDSM_X4(afl[mt], aL + so);
            }
#pragma unroll
            for (int h = 0; h < 2; h++) {
                uint32_t o = bOff[h] + ks * 32, so = (o ^ ((o >> 3) & 0x70));
                LDSM_X4(bfh[h], bH + so);
                LDSM_X4(bfl[h], bL + so);
            }
#pragma unroll
            for (int mt = 0; mt < 2; mt++)
#pragma unroll
                for (int nt = 0; nt < 4; nt++) {
                    const int hb = nt >> 1, eb = (nt & 1) * 2;
                    MMA_TF32(acc[mt][nt], afl[mt], bfh[hb][eb], bfh[hb][eb + 1]);
                    MMA_TF32(acc[mt][nt], afh[mt], bfl[hb][eb], bfl[hb][eb + 1]);
                    MMA_TF32(acc[mt][nt], afh[mt], bfh[hb][eb], bfh[hb][eb + 1]);
                }
        }
        __syncthreads();
    }

    const int gid = lid >> 2, tig = lid & 3;
#pragma unroll
    for (int mt = 0; mt < 2; mt++)
#pragma unroll
        for (int nt = 0; nt < 4; nt++)
#pragma unroll
            for (int e = 0; e < 4; e++) {
                const int row = wm * 32 + mt * 16 + gid + (e >> 1) * 8;
                const int col = wn * 32 + nt * 8 + 2 * tig + (e & 1);
                const int m = m0 + row;
                const float v = acc[mt][nt][e];
                if (nc < 4) {
                    const int bb = m >> 11, j = m & 2047;
                    g_W3VTh[((size_t)(bb * 64 + col)) * Kk + j * 4 + nc] = __float2half_rn(v);
                } else if (nc < 8) {
                    g_W2V[(size_t)m * 256 + (nc - 4) * 64 + col] = v;
                } else {
                    g_T1[(size_t)m * 64 + col] = v;
                }
            }
}

// ---------------- main GEMM: fp16 m16n8k16, BM=64, 4 CTA/SM ----------------
// grid (32, Bdim, SPLITK) = 576 blocks, 256 threads (8 warps).
// Warp tile 16 rows x 32 n: wm = wid&3 (16-row slices), wn = wid>>2.
__global__ __launch_bounds__(256, 4)
void gemm_kernel(const float* __restrict__ A) {
    __shared__ __align__(128) uint8_t smemRaw[32768];  // A:2x8KB, B:2x8KB
    const uint32_t sm = smem_u32(smemRaw);
    const uint32_t sAu[2] = { sm, sm + 8192 };
    const uint32_t sBu[2] = { sm + 16384, sm + 24576 };
    float* degS = (float*)smemRaw;   // aliases sA0 after the main loop (64*4 floats)

    const int mtb = blockIdx.x, b = blockIdx.y, s = blockIdx.z;
    const int i0 = mtb * BM;
    const int t0 = (s * NKTILES) / SPLITK, t1 = ((s + 1) * NKTILES) / SPLITK;
    const int nkt = t1 - t0;
    const int tid = threadIdx.x, wid = tid >> 5, lid = tid & 31;
    const int wm = wid & 3, wn = wid >> 2;

    const float*  Ab = A + ((size_t)b * Nn + i0) * Kk;
    const __half* Bb = g_W3VTh + ((size_t)b * Cc) * Kk;

    float4 ra[4];
    auto loadA = [&](int kt) {
#pragma unroll
        for (int it = 0; it < 4; it++) {
            const int idx = it * 256 + tid, row = idx >> 4, f4 = idx & 15;
            ra[it] = *(const float4*)(Ab + (size_t)row * Kk + kt * BKH + f4 * 4);
        }
    };
    auto stageA = [&](int st) {
#pragma unroll
        for (int it = 0; it < 4; it++) {
            const int idx = it * 256 + tid, row = idx >> 4, f4 = idx & 15;
            const uint32_t off = sw128((uint32_t)(row * 128 + f4 * 8));
            uint2 hv;
            hv.x = f22h2(ra[it].x, ra[it].y);
            hv.y = f22h2(ra[it].z, ra[it].w);
            *(uint2*)(smemRaw + st * 8192 + off) = hv;
        }
    };
    auto issueB = [&](int kt, int st) {
#pragma unroll
        for (int it = 0; it < 2; it++) {
            const int idx = it * 256 + tid, row = idx >> 3, seg = idx & 7;
            CP16(sBu[st] + sw128((uint32_t)(row * 128 + seg * 16)),
                 Bb + (size_t)row * Kk + kt * BKH + seg * 8);
        }
    };

    const uint32_t lrow = (uint32_t)((lid & 7) + ((lid >> 3) & 1) * 8);
    const uint32_t lkof = (uint32_t)((lid >> 4) * 16);
    const uint32_t aOff = (wm * 16 + lrow) * 128 + lkof;
    uint32_t bOff[2];
#pragma unroll
    for (int h = 0; h < 2; h++)
        bOff[h] = (wn * 32 + h * 16 + lrow) * 128 + lkof;

    float acc[4][4];
#pragma unroll
    for (int nt = 0; nt < 4; nt++)
#pragma unroll
        for (int e = 0; e < 4; e++) acc[nt][e] = 0.f;
    float2 dacc[2];
    dacc[0].x = dacc[0].y = dacc[1].x = dacc[1].y = 0.f;

    loadA(t0);
    issueB(t0, 0); CPCOMMIT();
    if (nkt > 1) issueB(t0 + 1, 1);
    CPCOMMIT();

    for (int qq = 0; qq < nkt; qq++) {
        const int st = qq & 1;
        stageA(st);
        if (qq + 1 < nkt) loadA(t0 + qq + 1);
        CPWAIT(1);
        __syncthreads();

#pragma unroll
        for (int ks = 0; ks < 4; ks++) {
            uint32_t af[4], bf[2][4];
            {
                uint32_t o = aOff + ks * 32;
                LDSM_X4(af, sAu[st] + (o ^ ((o >> 3) & 0x70)));
            }
#pragma unroll
            for (int h = 0; h < 2; h++) {
                uint32_t o = bOff[h] + ks * 32;
                LDSM_X4(bf[h], sBu[st] + (o ^ ((o >> 3) & 0x70)));
            }
            if (wn == 0) {   // deg: fp16 pair has k&3 = 2*(lid&1) + {0,1}
#pragma unroll
                for (int r = 0; r < 4; r++) {
                    const __half2 h = *(__half2*)&af[r];
                    const float2 f = __half22float2(h);
                    dacc[r & 1].x += f.x;
                    dacc[r & 1].y += f.y;
                }
            }
#pragma unroll
            for (int nt = 0; nt < 4; nt++)
                MMA_F16(acc[nt], af, bf[nt >> 1][nt & 1], bf[nt >> 1][(nt & 1) + 2]);
        }
        __syncthreads();
        if (qq + 2 < nkt) issueB(t0 + qq + 2, st);
        CPCOMMIT();
    }

    // deg: combine lanes l and l^2, then unique writes
    if (wn == 0) {
#pragma unroll
        for (int rh = 0; rh < 2; rh++) {
            float sx = dacc[rh].x + __shfl_xor_sync(0xFFFFFFFFu, dacc[rh].x, 2);
            float sy = dacc[rh].y + __shfl_xor_sync(0xFFFFFFFFu, dacc[rh].y, 2);
            if ((lid & 2) == 0) {
                const int row = wm * 16 + rh * 8 + (lid >> 2);
                const int e0 = 2 * (lid & 1);
                degS[row * 4 + e0]     = sx;
                degS[row * 4 + e0 + 1] = sy;
            }
        }
    }
    __syncthreads();

    // write partials
    const int gid = lid >> 2, tig = lid & 3;
    float* outp = g_part + (((size_t)s * Bdim + b) * Nn + i0) * PARTW;
#pragma unroll
    for (int nt = 0; nt < 4; nt++) {
        const int r0 = wm * 16 + gid;
        const int cc = wn * 32 + nt * 8 + 2 * tig;
        float2 v0; v0.x = acc[nt][0]; v0.y = acc[nt][1];
        float2 v1; v1.x = acc[nt][2]; v1.y = acc[nt][3];
        *(float2*)(outp + (size_t)r0 * PARTW + cc)       = v0;
        *(float2*)(outp + (size_t)(r0 + 8) * PARTW + cc) = v1;
    }
    if (tid < BM * Ll)   // 256 = 64*4
        outp[(size_t)(tid >> 2) * PARTW + 64 + (tid & 3)] = degS[tid];
}

// ---------------- epilogue: 1 channel/thread, 4 rows/block ----------------
// grid (Nn/4, Bdim) = 1024 blocks, 256 threads.
__global__ __launch_bounds__(256)
void epilogue_kernel(float* __restrict__ out) {
    __shared__ float sdeg[4][SPLITK][4];
    const int tid = threadIdx.x;
    const int c = tid & 63, r = tid >> 6;
    const int i = blockIdx.x * 4 + r, b = blockIdx.y;
    const size_t row = (size_t)b * Nn + i;
    const size_t stride = (size_t)Bdim * Nn * PARTW;
    const float* base = g_part + ((size_t)b * Nn + i) * PARTW;

    if (c < SPLITK)
        *(float4*)&sdeg[r][c][0] = *(const float4*)(base + c * stride + 64);

    float v[SPLITK];
#pragma unroll
    for (int s = 0; s < SPLITK; s++)
        v[s] = __ldg(base + s * stride + c);

    __syncthreads();
    float d0 = 0.f, d1 = 0.f, d2 = 0.f, d3 = 0.f, t3 = 0.f;
#pragma unroll
    for (int s = 0; s < SPLITK; s++) {
        t3 += v[s];
        d0 += sdeg[r][s][0]; d1 += sdeg[r][s][1];
        d2 += sdeg[r][s][2]; d3 += sdeg[r][s][3];
    }

    const float* w2v = g_W2V + row * (Ll * Cc);
    const float x = g_T1[row * Cc + c]
                  + d0 * w2v[0 * Cc + c] + d1 * w2v[1 * Cc + c]
                  + d2 * w2v[2 * Cc + c] + d3 * w2v[3 * Cc + c]
                  - t3;
    out[row * Cc + c] = 1.f / (1.f + expf(-x));
}

// ---------------- launch ----------------
extern "C" void kernel_launch(void* const* d_in, const int* in_sizes, int n_in,
                              void* d_out, int out_size) {
    const float* V  = (const float*)d_in[0];
    const float* A  = (const float*)d_in[1];
    const float* w1 = (const float*)d_in[2];
    const float* w2 = (const float*)d_in[3];
    const float* w3 = (const float*)d_in[4];
    float* out = (float*)d_out;

    wtrans_kernel<<<576, 64>>>(w1, w2, w3);
    pregemm_kernel<<<dim3(32, 9), 256>>>(V);
    gemm_kernel<<<dim3(Nn / BM, Bdim, SPLITK), 256>>>(A);
    epilogue_kernel<<<dim3(Nn / 4, Bdim), 256>>>(out);
}

// round 10
// speedup vs baseline: 1.1110x; 1.0353x over previous
#include <cuda_runtime.h>
#include <cuda_fp16.h>
#include <cstdint>
#include <math.h>

// ---------------- problem constants ----------------
#define Bdim 2
#define Nn   2048
#define Ff   64
#define Cc   64
#define Ll   4
#define Kk   (Nn*Ll)            // 8192
#define BM 64                   // rows per block (4 CTA/SM)
#define BKH 64                  // fp16 k-elements per tile (128 B rows)
#define NKTILES (Kk/BKH)        // 128
#define SPLITK 9                // 32 mtiles*2*9 = 576 blocks = 1 wave @ 4 CTA/SM

// ---------------- scratch (static device globals) ----------------
__device__ __align__(16) __half g_W3VTh[(size_t)Bdim*Cc*Kk];     // [b][c][k] fp16
__device__ __align__(16) float g_W2V [(size_t)Bdim*Nn*Ll*Cc];    // [m][l*64+c]
__device__ __align__(16) float g_accum[(size_t)Bdim*Nn*Cc];      // T1 - term3 (atomic)
__device__ __align__(16) float g_deg [(size_t)Bdim*Nn*Ll];       // deg (atomic)
__device__ __align__(16) float g_WTh [576*Ff];                   // tf32 hi
__device__ __align__(16) float g_WTl [576*Ff];                   // tf32 lo

// ---------------- helpers ----------------
__device__ __forceinline__ uint32_t smem_u32(const void* p) {
    uint32_t a;
    asm("{ .reg .u64 t; cvta.to.shared.u64 t, %1; cvt.u32.u64 %0, t; }" : "=r"(a) : "l"(p));
    return a;
}
__device__ __forceinline__ float to_tf32(float x) {
    uint32_t u;
    asm("cvt.rna.tf32.f32 %0, %1;" : "=r"(u) : "f"(x));
    return __uint_as_float(u);
}
__device__ __forceinline__ uint32_t sw128(uint32_t off) { return off ^ ((off >> 3) & 0x70); }
__device__ __forceinline__ uint32_t f22h2(float x, float y) {
    __half2 h = __floats2half2_rn(x, y);
    return *(uint32_t*)&h;
}

#define CP16(dst, src) \
    asm volatile("cp.async.cg.shared.global [%0], [%1], 16;" \
        :: "r"(dst), "l"(__cvta_generic_to_global(src)) : "memory")
#define CPCOMMIT() asm volatile("cp.async.commit_group;" ::: "memory")
#define CPWAIT(n)  asm volatile("cp.async.wait_group %0;" :: "n"(n) : "memory")

#define RED2(addr, x, y) \
    asm volatile("red.global.add.v2.f32 [%0], {%1, %2};" \
        :: "l"(addr), "f"(x), "f"(y) : "memory")

#define LDSM_X4(r, addr)                                                         \
    asm volatile("ldmatrix.sync.aligned.m8n8.x4.shared.b16 {%0,%1,%2,%3}, [%4];" \
        : "=r"((r)[0]), "=r"((r)[1]), "=r"((r)[2]), "=r"((r)[3]) : "r"(addr))

#define MMA_TF32(c, a, b0v, b1v)                                                 \
    asm volatile("mma.sync.aligned.m16n8k8.row.col.f32.tf32.tf32.f32 "           \
        "{%0,%1,%2,%3}, {%4,%5,%6,%7}, {%8,%9}, {%0,%1,%2,%3};"                  \
        : "+f"((c)[0]), "+f"((c)[1]), "+f"((c)[2]), "+f"((c)[3])                  \
        : "r"((a)[0]), "r"((a)[1]), "r"((a)[2]), "r"((a)[3]), "r"(b0v), "r"(b1v))

#define MMA_F16(c, a, b0v, b1v)                                                  \
    asm volatile("mma.sync.aligned.m16n8k16.row.col.f32.f16.f16.f32 "            \
        "{%0,%1,%2,%3}, {%4,%5,%6,%7}, {%8,%9}, {%0,%1,%2,%3};"                  \
        : "+f"((c)[0]), "+f"((c)[1]), "+f"((c)[2]), "+f"((c)[3])                  \
        : "r"((a)[0]), "r"((a)[1]), "r"((a)[2]), "r"((a)[3]), "r"(b0v), "r"(b1v))

// ---------------- weight transpose/concat + tf32 split + g_deg zero ----------------
__global__ void wtrans_kernel(const float* __restrict__ w1,
                              const float* __restrict__ w2,
                              const float* __restrict__ w3) {
    const int t = blockIdx.x, f = threadIdx.x;
    float v;
    if (t < 256)      v = w3[((t >> 6) * Ff + f) * Cc + (t & 63)];
    else if (t < 512) v = w2[(((t - 256) >> 6) * Ff + f) * Cc + ((t - 256) & 63)];
    else              v = w1[f * Cc + (t - 512)];
    const float hi = to_tf32(v);
    g_WTh[t * Ff + f] = hi;
    g_WTl[t * Ff + f] = to_tf32(v - hi);
    if (t < 256) g_deg[t * 64 + f] = 0.f;   // 256*64 = 16384 = Bdim*Nn*Ll
}

// ---------------- precompute GEMM (tf32x3): [W3V | W2V | T1->accum] = V @ Wcat ----------------
// grid (32 M-tiles of 128 rows, 9 N-chunks), 256 threads.
__global__ __launch_bounds__(256)
void pregemm_kernel(const float* __restrict__ V) {
    __shared__ __align__(128) float sAhi[128 * 32];
    __shared__ __align__(128) float sAlo[128 * 32];
    __shared__ __align__(128) float sBhi[64 * 32];
    __shared__ __align__(128) float sBlo[64 * 32];
    const uint32_t aH = smem_u32(sAhi), aL = smem_u32(sAlo);
    const uint32_t bH = smem_u32(sBhi), bL = smem_u32(sBlo);

    const int mtile = blockIdx.x, nc = blockIdx.y;
    const int m0 = mtile * 128;
    const int tid = threadIdx.x, wid = tid >> 5, lid = tid & 31;
    const int wm = wid & 3, wn = wid >> 2;

    const float* Ab  = V + (size_t)m0 * Ff;
    const float* Bh  = g_WTh + (size_t)nc * 64 * Ff;
    const float* Bl  = g_WTl + (size_t)nc * 64 * Ff;

    const int q = lid >> 3, rr = lid & 7;
    uint32_t aOff[2], bOff[2];
#pragma unroll
    for (int mt = 0; mt < 2; mt++)
        aOff[mt] = (uint32_t)((wm * 32 + mt * 16 + rr + (q & 1) * 8) * 128 + (q >> 1) * 16);
#pragma unroll
    for (int h = 0; h < 2; h++)
        bOff[h]  = (uint32_t)((wn * 32 + h * 16 + rr + (q >> 1) * 8) * 128 + (q & 1) * 16);

    float acc[2][4][4];
#pragma unroll
    for (int mt = 0; mt < 2; mt++)
#pragma unroll
        for (int nt = 0; nt < 4; nt++)
#pragma unroll
            for (int e = 0; e < 4; e++) acc[mt][nt][e] = 0.f;

    for (int kt = 0; kt < 2; kt++) {
#pragma unroll
        for (int it = 0; it < 4; it++) {
            const int idx = it * 256 + tid, row = idx >> 3, f4 = idx & 7;
            const float4 v = *(const float4*)(Ab + (size_t)row * Ff + kt * 32 + f4 * 4);
            float4 h, l;
            h.x = to_tf32(v.x); l.x = to_tf32(v.x - h.x);
            h.y = to_tf32(v.y); l.y = to_tf32(v.y - h.y);
            h.z = to_tf32(v.z); l.z = to_tf32(v.z - h.z);
            h.w = to_tf32(v.w); l.w = to_tf32(v.w - h.w);
            const uint32_t off = sw128((uint32_t)(row * 128 + f4 * 16));
            *(float4*)((char*)sAhi + off) = h;
            *(float4*)((char*)sAlo + off) = l;
        }
#pragma unroll
        for (int it = 0; it < 2; it++) {
            const int idx = it * 256 + tid, row = idx >> 3, f4 = idx & 7;
            const uint32_t off = sw128((uint32_t)(row * 128 + f4 * 16));
            *(float4*)((char*)sBhi + off) = *(const float4*)(Bh + (size_t)row * Ff + kt * 32 + f4 * 4);
            *(float4*)((char*)sBlo + off) = *(const float4*)(Bl + (size_t)row * Ff + kt * 32 + f4 * 4);
        }
        __syncthreads();

#pragma unroll
        for (int ks = 0; ks < 4; ks++) {
            uint32_t afh[2][4], afl[2][4], bfh[2][4], bfl[2][4];
#pragma unroll
            for (int mt = 0; mt < 2; mt++) {
                uint32_t o = aOff[mt] + ks * 32, so = (o ^ ((o >> 3) & 0x70));
                LDSM_X4(afh[mt], aH + so);
                LDSM_X4(afl[mt], aL + so);
            }
#pragma unroll
            for (int h = 0; h < 2; h++) {
                uint32_t o = bOff[h] + ks * 32, so = (o ^ ((o >> 3) & 0x70));
                LDSM_X4(bfh[h], bH + so);
                LDSM_X4(bfl[h], bL + so);
            }
#pragma unroll
            for (int mt = 0; mt < 2; mt++)
#pragma unroll
                for (int nt = 0; nt < 4; nt++) {
                    const int hb = nt >> 1, eb = (nt & 1) * 2;
                    MMA_TF32(acc[mt][nt], afl[mt], bfh[hb][eb], bfh[hb][eb + 1]);
                    MMA_TF32(acc[mt][nt], afh[mt], bfl[hb][eb], bfl[hb][eb + 1]);
                    MMA_TF32(acc[mt][nt], afh[mt], bfh[hb][eb], bfh[hb][eb + 1]);
                }
        }
        __syncthreads();
    }

    const int gid = lid >> 2, tig = lid & 3;
#pragma unroll
    for (int mt = 0; mt < 2; mt++)
#pragma unroll
        for (int nt = 0; nt < 4; nt++)
#pragma unroll
            for (int e = 0; e < 4; e++) {
                const int row = wm * 32 + mt * 16 + gid + (e >> 1) * 8;
                const int col = wn * 32 + nt * 8 + 2 * tig + (e & 1);
                const int m = m0 + row;
                const float v = acc[mt][nt][e];
                if (nc < 4) {
                    const int bb = m >> 11, j = m & 2047;
                    g_W3VTh[((size_t)(bb * 64 + col)) * Kk + j * 4 + nc] = __float2half_rn(v);
                } else if (nc < 8) {
                    g_W2V[(size_t)m * 256 + (nc - 4) * 64 + col] = v;
                } else {
                    g_accum[(size_t)m * 64 + col] = v;   // T1 seeds the accumulator
                }
            }
}

// ---------------- main GEMM: fp16 m16n8k16, BM=64, split-K fused via L2 atomics ----------------
// grid (32, Bdim, SPLITK) = 576 blocks, 256 threads (8 warps).
__global__ __launch_bounds__(256, 4)
void gemm_kernel(const float* __restrict__ A) {
    __shared__ __align__(128) uint8_t smemRaw[32768];  // A:2x8KB, B:2x8KB
    const uint32_t sm = smem_u32(smemRaw);
    const uint32_t sAu[2] = { sm, sm + 8192 };
    const uint32_t sBu[2] = { sm + 16384, sm + 24576 };

    const int mtb = blockIdx.x, b = blockIdx.y, s = blockIdx.z;
    const int i0 = mtb * BM;
    const int t0 = (s * NKTILES) / SPLITK, t1 = ((s + 1) * NKTILES) / SPLITK;
    const int nkt = t1 - t0;
    const int tid = threadIdx.x, wid = tid >> 5, lid = tid & 31;
    const int wm = wid & 3, wn = wid >> 2;

    const float*  Ab = A + ((size_t)b * Nn + i0) * Kk;
    const __half* Bb = g_W3VTh + ((size_t)b * Cc) * Kk;

    float4 ra[4];
    auto loadA = [&](int kt) {
#pragma unroll
        for (int it = 0; it < 4; it++) {
            const int idx = it * 256 + tid, row = idx >> 4, f4 = idx & 15;
            ra[it] = *(const float4*)(Ab + (size_t)row * Kk + kt * BKH + f4 * 4);
        }
    };
    auto stageA = [&](int st) {
#pragma unroll
        for (int it = 0; it < 4; it++) {
            const int idx = it * 256 + tid, row = idx >> 4, f4 = idx & 15;
            const uint32_t off = sw128((uint32_t)(row * 128 + f4 * 8));
            uint2 hv;
            hv.x = f22h2(ra[it].x, ra[it].y);
            hv.y = f22h2(ra[it].z, ra[it].w);
            *(uint2*)(smemRaw + st * 8192 + off) = hv;
        }
    };
    auto issueB = [&](int kt, int st) {
#pragma unroll
        for (int it = 0; it < 2; it++) {
            const int idx = it * 256 + tid, row = idx >> 3, seg = idx & 7;
            CP16(sBu[st] + sw128((uint32_t)(row * 128 + seg * 16)),
                 Bb + (size_t)row * Kk + kt * BKH + seg * 8);
        }
    };

    const uint32_t lrow = (uint32_t)((lid & 7) + ((lid >> 3) & 1) * 8);
    const uint32_t lkof = (uint32_t)((lid >> 4) * 16);
    const uint32_t aOff = (wm * 16 + lrow) * 128 + lkof;
    uint32_t bOff[2];
#pragma unroll
    for (int h = 0; h < 2; h++)
        bOff[h] = (wn * 32 + h * 16 + lrow) * 128 + lkof;

    float acc[4][4];
#pragma unroll
    for (int nt = 0; nt < 4; nt++)
#pragma unroll
        for (int e = 0; e < 4; e++) acc[nt][e] = 0.f;
    float2 dacc[2];
    dacc[0].x = dacc[0].y = dacc[1].x = dacc[1].y = 0.f;

    loadA(t0);
    issueB(t0, 0); CPCOMMIT();
    if (nkt > 1) issueB(t0 + 1, 1);
    CPCOMMIT();

    for (int qq = 0; qq < nkt; qq++) {
        const int st = qq & 1;
        stageA(st);
        if (qq + 1 < nkt) loadA(t0 + qq + 1);
        CPWAIT(1);
        __syncthreads();

#pragma unroll
        for (int ks = 0; ks < 4; ks++) {
            uint32_t af[4], bf[2][4];
            {
                uint32_t o = aOff + ks * 32;
                LDSM_X4(af, sAu[st] + (o ^ ((o >> 3) & 0x70)));
            }
#pragma unroll
            for (int h = 0; h < 2; h++) {
                uint32_t o = bOff[h] + ks * 32;
                LDSM_X4(bf[h], sBu[st] + (o ^ ((o >> 3) & 0x70)));
            }
            if (wn == 0) {   // deg: fp16 pair has k&3 = 2*(lid&1) + {0,1}
#pragma unroll
                for (int r = 0; r < 4; r++) {
                    const __half2 h = *(__half2*)&af[r];
                    const float2 f = __half22float2(h);
                    dacc[r & 1].x += f.x;
                    dacc[r & 1].y += f.y;
                }
            }
#pragma unroll
            for (int nt = 0; nt < 4; nt++)
                MMA_F16(acc[nt], af, bf[nt >> 1][nt & 1], bf[nt >> 1][(nt & 1) + 2]);
        }
        __syncthreads();
        if (qq + 2 < nkt) issueB(t0 + qq + 2, st);
        CPCOMMIT();
    }

    // deg: combine lanes l and l^2, atomically add to g_deg
    if (wn == 0) {
#pragma unroll
        for (int rh = 0; rh < 2; rh++) {
            float sx = dacc[rh].x + __shfl_xor_sync(0xFFFFFFFFu, dacc[rh].x, 2);
            float sy = dacc[rh].y + __shfl_xor_sync(0xFFFFFFFFu, dacc[rh].y, 2);
            if ((lid & 2) == 0) {
                const int row = wm * 16 + rh * 8 + (lid >> 2);
                const int e0 = 2 * (lid & 1);
                RED2(g_deg + ((size_t)b * Nn + i0 + row) * Ll + e0, sx, sy);
            }
        }
    }

    // term3: atomically subtract from g_accum (L2-resident, 2 MB target)
    const int gid = lid >> 2, tig = lid & 3;
    float* accp = g_accum + ((size_t)b * Nn + i0) * Cc;
#pragma unroll
    for (int nt = 0; nt < 4; nt++) {
        const int r0 = wm * 16 + gid;
        const int cc = wn * 32 + nt * 8 + 2 * tig;
        RED2(accp + (size_t)r0 * Cc + cc,       -acc[nt][0], -acc[nt][1]);
        RED2(accp + (size_t)(r0 + 8) * Cc + cc, -acc[nt][2], -acc[nt][3]);
    }
}

// ---------------- epilogue: x = accum + deg.W2V, sigmoid ----------------
// grid (Nn/4, Bdim), 256 threads: 4 rows/block, 1 channel/thread.
__global__ __launch_bounds__(256)
void epilogue_kernel(float* __restrict__ out) {
    const int tid = threadIdx.x;
    const int c = tid & 63, r = tid >> 6;
    const int i = blockIdx.x * 4 + r, b = blockIdx.y;
    const size_t row = (size_t)b * Nn + i;

    const float4 dv = *(const float4*)(g_deg + row * Ll);
    const float* w2v = g_W2V + row * (Ll * Cc);
    const float x = g_accum[row * Cc + c]
                  + dv.x * w2v[0 * Cc + c] + dv.y * w2v[1 * Cc + c]
                  + dv.z * w2v[2 * Cc + c] + dv.w * w2v[3 * Cc + c];
    out[row * Cc + c] = 1.f / (1.f + expf(-x));
}

// ---------------- launch ----------------
extern "C" void kernel_launch(void* const* d_in, const int* in_sizes, int n_in,
                              void* d_out, int out_size) {
    const float* V  = (const float*)d_in[0];
    const float* A  = (const float*)d_in[1];
    const float* w1 = (const float*)d_in[2];
    const float* w2 = (const float*)d_in[3];
    const float* w3 = (const float*)d_in[4];
    float* out = (float*)d_out;

    wtrans_kernel<<<576, 64>>>(w1, w2, w3);
    pregemm_kernel<<<dim3(32, 9), 256>>>(V);
    gemm_kernel<<<dim3(Nn / BM, Bdim, SPLITK), 256>>>(A);
    epilogue_kernel<<<dim3(Nn / 4, Bdim), 256>>>(out);
}